// round 10
// baseline (speedup 1.0000x reference)
#include <cuda_runtime.h>
#include <cuda_bf16.h>
#include <cstdint>

typedef uint32_t u32; typedef uint64_t u64;

#define NVERT 20000
#define NDIRS 8
#define THREADS 256
#define VTILE 32              // vertices per CTA  -> 64 m-rows
#define NTILES 625            // 20000/32 exact
#define NCHUNKS 9             // 8 rings + 1 center chunk, Kc=128 each

// ---- B chunk images (hi/lo bf16), pre-swizzled, rebuilt each launch ----
__device__ __align__(16) __nv_bfloat16 gBh[NCHUNKS][16384];   // [chunk][128n x 128k]
__device__ __align__(16) __nv_bfloat16 gBl[NCHUNKS][16384];

// element (row,k) byte offset in a row-major tile: row stride 256B,
// 16B chunks XOR-swizzled by (row&7) -> conflict-free LDSM
__device__ __host__ __forceinline__ u32 tile_off(int row, int k) {
    return (u32)(row * 256 + (((k >> 3) ^ (row & 7)) << 4) + (k & 7) * 2);
}

__device__ __forceinline__ u32 smem_u32(const void* p) {
    u32 a; asm("{ .reg .u64 t; cvta.to.shared.u64 t, %1; cvt.u32.u64 %0, t; }" : "=r"(a) : "l"(p));
    return a;
}
__device__ __forceinline__ void ldsm4(u32 r[4], u32 addr) {
    asm volatile("ldmatrix.sync.aligned.m8n8.x4.shared.b16 {%0,%1,%2,%3}, [%4];"
                 : "=r"(r[0]), "=r"(r[1]), "=r"(r[2]), "=r"(r[3]) : "r"(addr));
}
__device__ __forceinline__ void mma16816(float c[4], const u32 a[4], u32 b0, u32 b1) {
    asm volatile(
        "mma.sync.aligned.m16n8k16.row.col.f32.bf16.bf16.f32 "
        "{%0,%1,%2,%3}, {%4,%5,%6,%7}, {%8,%9}, {%0,%1,%2,%3};"
        : "+f"(c[0]), "+f"(c[1]), "+f"(c[2]), "+f"(c[3])
        : "r"(a[0]), "r"(a[1]), "r"(a[2]), "r"(a[3]), "r"(b0), "r"(b1));
}
__device__ __forceinline__ void cp16(u32 dst, const void* src) {
    asm volatile("cp.async.cg.shared.global [%0], [%1], 16;" :: "r"(dst), "l"(src) : "memory");
}
__device__ __forceinline__ void cp_commit_waitall() {
    asm volatile("cp.async.commit_group;\n\tcp.async.wait_group 0;" ::: "memory");
}

// ---- prep kernel: build swizzled bf16 hi/lo B-chunk images ----
// n = f*8 + d ; k = dp*16 + c
__global__ void prep_B(const float* __restrict__ kern, const float* __restrict__ ck) {
    int id = blockIdx.x * blockDim.x + threadIdx.x;     // 147456
    if (id >= NCHUNKS * 128 * 128) return;
    int k  = id & 127;
    int n  = (id >> 7) & 127;
    int kc = id >> 14;
    int f = n >> 3, d = n & 7;
    int dp = k >> 4, c = k & 15;
    float val;
    if (kc < 8) {
        int dw = (dp - d) & 7;
        val = kern[((kc * 8 + dw) * 16 + c) * 16 + f];
    } else {
        val = (dp == d) ? ck[c * 16 + f] : 0.f;
    }
    __nv_bfloat16 hi = __float2bfloat16(val);
    __nv_bfloat16 lo = __float2bfloat16(val - __bfloat162float(hi));
    u32 e = tile_off(n, k) >> 1;
    gBh[kc][e] = hi;
    gBl[kc][e] = lo;
}

// ---- smem layout (byte offsets): A 64x128 hi/lo + B 128x128 hi/lo = 96 KB ----
#define SAH 0
#define SAL 16384
#define SBH 32768
#define SBL 65536
#define SMEM_TOTAL 98304
#define A_LO_OFF 16384
#define B_LO_OFF 32768

// convert 4 floats (k-quad q of row m) to hi/lo bf16 and store 8B each image
__device__ __forceinline__ void store_quad(char* sm, int m, int dp, int q, float4 z) {
    __nv_bfloat162 h0 = __floats2bfloat162_rn(z.x, z.y);
    __nv_bfloat162 h1 = __floats2bfloat162_rn(z.z, z.w);
    __nv_bfloat162 l0 = __floats2bfloat162_rn(z.x - __low2float(h0), z.y - __high2float(h0));
    __nv_bfloat162 l1 = __floats2bfloat162_rn(z.z - __low2float(h1), z.w - __high2float(h1));
    u32 off = (u32)(m * 256 + ((((dp << 1) | (q >> 1)) ^ (m & 7)) << 4) + (q & 1) * 8);
    uint2 H; H.x = *reinterpret_cast<u32*>(&h0); H.y = *reinterpret_cast<u32*>(&h1);
    uint2 L; L.x = *reinterpret_cast<u32*>(&l0); L.y = *reinterpret_cast<u32*>(&l1);
    *reinterpret_cast<uint2*>(sm + SAH + off) = H;
    *reinterpret_cast<uint2*>(sm + SAL + off) = L;
}

__global__ __launch_bounds__(THREADS, 2)
void geodesic_hmma_kernel(const float* __restrict__ y,
                          const int*   __restrict__ contributors,
                          const float* __restrict__ weights_bary,
                          const int*   __restrict__ angles,
                          const float* __restrict__ bias,
                          float*       __restrict__ out)
{
    extern __shared__ char sm[];
    const u32 smb = smem_u32(sm);
    const int tid = threadIdx.x;
    const int wid = tid >> 5;
    const int lid = tid & 31;
    const int v0  = blockIdx.x * VTILE;         // 32 vertices => 64 rows (m = vl*2 + b)
    const int m0  = (wid >> 1) * 16;            // warp's 16-row m-strip (4 strips)
    const int nh  = wid & 1;                    // warp's n-half (64 cols)

    // accumulators: 8 n-tiles x 4 fp32
    float acc[32];
    #pragma unroll
    for (int i = 0; i < 32; ++i) acc[i] = 0.f;

    const int lrow  = (lid & 7) + ((lid >> 3) & 1) * 8;
    const int khalf = (lid >> 4);

    // hoisted ldmatrix addressing: base + (cc4 ^ xorm), lo-image at fixed offset
    const int mA = m0 + lrow;
    const u32 a_base = smb + SAH + (u32)(mA * 256);
    const u32 a_xor  = (u32)((mA & 7) << 4);
    u32 b_base[4], b_xor[4];
    #pragma unroll
    for (int p = 0; p < 4; ++p) {
        int nB = nh*64 + p*16 + lrow;
        b_base[p] = smb + SBH + (u32)(nB * 256);
        b_xor[p]  = (u32)((nB & 7) << 4);
    }

    // quad-cooperative gather geometry
    const int q     = lid & 3;                  // c-quad (16B) within row
    const int qt    = tid >> 2;                 // quad id 0..63
    const int lbase = lid & ~3;                 // quad's first lane in warp

    const float4* y4 = (const float4*)y;

    #pragma unroll 1
    for (int kc = 0; kc < NCHUNKS; ++kc) {
        if (kc > 0) __syncthreads();       // everyone done reading A and B of prev chunk

        // ---- issue async B-chunk copy first (hides under gather) ----
        {
            const char* sh = (const char*)(&gBh[kc][0]);
            const char* sl = (const char*)(&gBl[kc][0]);
            #pragma unroll
            for (int i = 0; i < 8; ++i) {
                u32 off = (u32)(tid + i * THREADS) * 16;
                cp16(smb + SBH + off, sh + off);
                cp16(smb + SBL + off, sl + off);
            }
        }

        // ---- gather: one (v,dp) task per QUAD; lane q owns 16B c-quad ----
        if (kc < 8) {
            // prefetch index/weight for ALL 4 rr-tasks (12 independent LDGs in flight)
            int   pidx[4];
            float pw[4];
            #pragma unroll
            for (int rr = 0; rr < 4; ++rr) {
                int t  = qt + rr * 64;
                int dp = t & 7;
                int vl = t >> 3;
                int v  = v0 + vl;
                int ibase = ((v * 8 + kc) * 8 + dp) * 3;
                if (q < 3) {
                    pidx[rr] = __ldg(&contributors[ibase + q]) * 8 + __ldg(&angles[ibase + q]);
                    pw[rr]   = __ldg(&weights_bary[ibase + q]);
                } else { pidx[rr] = 0; pw[rr] = 0.f; }
            }
            // y loads + combine + store, 2 tasks in flight (12 LDG.128)
            #pragma unroll 2
            for (int rr = 0; rr < 4; ++rr) {
                int t  = qt + rr * 64;
                int dp = t & 7;
                int vl = t >> 3;
                int   i0 = __shfl_sync(0xffffffffu, pidx[rr], lbase + 0);
                int   i1 = __shfl_sync(0xffffffffu, pidx[rr], lbase + 1);
                int   i2 = __shfl_sync(0xffffffffu, pidx[rr], lbase + 2);
                float w0 = __shfl_sync(0xffffffffu, pw[rr],   lbase + 0);
                float w1 = __shfl_sync(0xffffffffu, pw[rr],   lbase + 1);
                float w2 = __shfl_sync(0xffffffffu, pw[rr],   lbase + 2);
                float4 a0 = __ldg(y4 + (u32)i0 * 4 + q);
                float4 a1 = __ldg(y4 + (u32)i1 * 4 + q);
                float4 a2 = __ldg(y4 + (u32)i2 * 4 + q);
                float4 c0 = __ldg(y4 + (u32)i0 * 4 + q + NVERT * NDIRS * 4);
                float4 c1 = __ldg(y4 + (u32)i1 * 4 + q + NVERT * NDIRS * 4);
                float4 c2 = __ldg(y4 + (u32)i2 * 4 + q + NVERT * NDIRS * 4);
                float4 z0, z1;
                z0.x = w0*a0.x + w1*a1.x + w2*a2.x;
                z0.y = w0*a0.y + w1*a1.y + w2*a2.y;
                z0.z = w0*a0.z + w1*a1.z + w2*a2.z;
                z0.w = w0*a0.w + w1*a1.w + w2*a2.w;
                z1.x = w0*c0.x + w1*c1.x + w2*c2.x;
                z1.y = w0*c0.y + w1*c1.y + w2*c2.y;
                z1.z = w0*c0.z + w1*c1.z + w2*c2.z;
                z1.w = w0*c0.w + w1*c1.w + w2*c2.w;
                store_quad(sm, vl*2 + 0, dp, q, z0);
                store_quad(sm, vl*2 + 1, dp, q, z1);
            }
        } else {
            #pragma unroll
            for (int rr = 0; rr < 4; ++rr) {
                int t  = qt + rr * 64;
                int dp = t & 7;
                int vl = t >> 3;
                int v  = v0 + vl;
                int idx = v * 8 + dp;
                float4 z0 = __ldg(y4 + (u32)idx * 4 + q);
                float4 z1 = __ldg(y4 + (u32)idx * 4 + q + NVERT * NDIRS * 4);
                store_quad(sm, vl*2 + 0, dp, q, z0);
                store_quad(sm, vl*2 + 1, dp, q, z1);
            }
        }

        cp_commit_waitall();
        __syncthreads();

        // ---- HMMA: batch-load frags, 24 MMAs at same-acc distance 8 ----
        #pragma unroll 1
        for (int ks = 0; ks < 8; ++ks) {
            u32 cc4 = (u32)((ks*2 + khalf) << 4);
            u32 aaddr = a_base + (cc4 ^ a_xor);
            u32 afh[4], afl[4];
            ldsm4(afh, aaddr);
            ldsm4(afl, aaddr + A_LO_OFF);
            u32 bfh[4][4], bfl[4][4];
            #pragma unroll
            for (int p = 0; p < 4; ++p) {
                u32 baddr = b_base[p] + (cc4 ^ b_xor[p]);
                ldsm4(bfh[p], baddr);
                ldsm4(bfl[p], baddr + B_LO_OFF);
            }
            #pragma unroll
            for (int p = 0; p < 4; ++p) mma16816(&acc[(p*2+0)*4], afh, bfh[p][0], bfh[p][2]);
            #pragma unroll
            for (int p = 0; p < 4; ++p) mma16816(&acc[(p*2+1)*4], afh, bfh[p][1], bfh[p][3]);
            #pragma unroll
            for (int p = 0; p < 4; ++p) mma16816(&acc[(p*2+0)*4], afh, bfl[p][0], bfl[p][2]);
            #pragma unroll
            for (int p = 0; p < 4; ++p) mma16816(&acc[(p*2+1)*4], afh, bfl[p][1], bfl[p][3]);
            #pragma unroll
            for (int p = 0; p < 4; ++p) mma16816(&acc[(p*2+0)*4], afl, bfh[p][0], bfh[p][2]);
            #pragma unroll
            for (int p = 0; p < 4; ++p) mma16816(&acc[(p*2+1)*4], afl, bfh[p][1], bfh[p][3]);
        }
    }

    // ---- epilogue: bias + relu + max over d ----
    // f = nh*8 + t ; d = (lid&3)*2 + {0,1}
    #pragma unroll
    for (int t = 0; t < 8; ++t) {
        int f = nh*8 + t;
        float mlo = fmaxf(acc[t*4+0], acc[t*4+1]);
        float mhi = fmaxf(acc[t*4+2], acc[t*4+3]);
        mlo = fmaxf(mlo, __shfl_xor_sync(0xffffffffu, mlo, 1));
        mlo = fmaxf(mlo, __shfl_xor_sync(0xffffffffu, mlo, 2));
        mhi = fmaxf(mhi, __shfl_xor_sync(0xffffffffu, mhi, 1));
        mhi = fmaxf(mhi, __shfl_xor_sync(0xffffffffu, mhi, 2));
        if ((lid & 3) == (t & 3)) {
            float bf_ = __ldg(&bias[f]);
            int r = m0 + (lid >> 2);
            int b = r & 1, v = v0 + (r >> 1);
            out[((u32)b * NVERT + v) * 16 + f] = fmaxf(mlo + bf_, 0.f);
            r += 8; b = r & 1; v = v0 + (r >> 1);
            out[((u32)b * NVERT + v) * 16 + f] = fmaxf(mhi + bf_, 0.f);
        }
    }
}

extern "C" void kernel_launch(void* const* d_in, const int* in_sizes, int n_in,
                              void* d_out, int out_size)
{
    (void)in_sizes; (void)n_in; (void)out_size;
    const float* y            = (const float*)d_in[0];
    const int*   contributors = (const int*)  d_in[1];
    const float* weights_bary = (const float*)d_in[2];
    const int*   angles       = (const int*)  d_in[3];
    const float* kern         = (const float*)d_in[4];
    const float* center_k     = (const float*)d_in[5];
    const float* bias         = (const float*)d_in[6];
    float* out = (float*)d_out;

    prep_B<<<(NCHUNKS*128*128 + 255)/256, 256>>>(kern, center_k);

    cudaFuncSetAttribute(geodesic_hmma_kernel,
                         cudaFuncAttributeMaxDynamicSharedMemorySize, SMEM_TOTAL);
    geodesic_hmma_kernel<<<NTILES, THREADS, SMEM_TOTAL>>>(
        y, contributors, weights_bary, angles, bias, out);
}